// round 15
// baseline (speedup 1.0000x reference)
#include <cuda_runtime.h>
#include <cuda_bf16.h>
#include <mma.h>
#include <cstdint>

using namespace nvcuda;

#define N_NODES 100000
#define N_EDGES 1600000
#define HID 64
#define NGRAPH 4096
#define BN_EPS 1e-5f
#define SCAN_B 1024
#define SCAN_NB ((N_NODES + SCAN_B - 1) / SCAN_B)   // 98
#define N_TILES (N_NODES / 16)                      // 6250 (exact)
#define GATH_GRID 592
#define GEMM_TILES ((N_NODES + 127) / 128)          // 782
#define GEMM_GRID 296

// ---------------- scratch (device globals; no allocations) ----------------
__device__ __align__(16) float g_h[(N_NODES + 1) * HID]; // h' = h*dinv (+zero row)
__device__ __align__(16) float g_y[N_NODES * HID];       // post-relu (pool input)
__device__ __align__(16) __nv_bfloat16 g_xhi[N_NODES * 80];
__device__ __align__(16) __nv_bfloat16 g_xlo[N_NODES * 80];
__device__ __align__(16) __nv_bfloat16 g_yhi[N_NODES * HID];
__device__ __align__(16) __nv_bfloat16 g_ylo[N_NODES * HID];
__device__ int   g_cnt[N_NODES];
__device__ float g_dinv[N_NODES];
__device__ int   g_rowptr[N_NODES];
__device__ int   g_cursor[N_NODES];
__device__ int   g_eidx[N_EDGES];
__device__ int   g_blksum[SCAN_NB];
__device__ float g_stats[2][2 * HID];

// ---------------- helpers ----------------
__device__ __forceinline__ unsigned smem_u32(const void* p) {
    return (unsigned)__cvta_generic_to_shared(p);
}
#define CP_ASYNC16(s, g) asm volatile("cp.async.cg.shared.global [%0], [%1], 16;" :: "r"(s), "l"(g) : "memory")
#define CP_COMMIT()      asm volatile("cp.async.commit_group;" ::: "memory")
#define CP_WAIT1()       asm volatile("cp.async.wait_group 1;" ::: "memory")

__device__ __forceinline__ uint32_t split_hi2(float a, float b, uint32_t& lo_out) {
    __nv_bfloat16 ha = __float2bfloat16(a);
    __nv_bfloat16 hb = __float2bfloat16(b);
    __nv_bfloat16 la = __float2bfloat16(a - __bfloat162float(ha));
    __nv_bfloat16 lb = __float2bfloat16(b - __bfloat162float(hb));
    __nv_bfloat162 h2; h2.x = ha; h2.y = hb;
    __nv_bfloat162 l2; l2.x = la; l2.y = lb;
    lo_out = *(uint32_t*)&l2;
    return *(uint32_t*)&h2;
}

// ---------------- CSR build ----------------
__global__ void hist_kernel(const int* __restrict__ dst) {
    int e = blockIdx.x * blockDim.x + threadIdx.x;
    if (e < N_EDGES) {
        asm volatile("red.global.add.u32 [%0], %1;"
                     :: "l"(&g_cnt[dst[e]]), "r"(1) : "memory");
    }
}

__global__ __launch_bounds__(SCAN_B) void scan1_kernel() {
    __shared__ int sm[SCAN_B];
    int t = threadIdx.x;
    int i = blockIdx.x * SCAN_B + t;
    int v = (i < N_NODES) ? g_cnt[i] : 0;
    sm[t] = v;
    __syncthreads();
    for (int off = 1; off < SCAN_B; off <<= 1) {
        int x = (t >= off) ? sm[t - off] : 0;
        __syncthreads();
        sm[t] += x;
        __syncthreads();
    }
    if (i < N_NODES) g_rowptr[i] = sm[t] - v;
    if (t == SCAN_B - 1) g_blksum[blockIdx.x] = sm[t];
}

__global__ __launch_bounds__(SCAN_B) void scan23_kernel() {
    __shared__ int sb[128];
    __shared__ int sv[128];
    int t = threadIdx.x;
    if (t < 128) {
        int v = (t < SCAN_NB) ? g_blksum[t] : 0;
        sb[t] = v;
        sv[t] = v;
    }
    __syncthreads();
    for (int off = 1; off < 128; off <<= 1) {
        int x = (t >= off && t < 128) ? sb[t - off] : 0;
        __syncthreads();
        if (t < 128) sb[t] += x;
        __syncthreads();
    }
    int offset = sb[blockIdx.x] - sv[blockIdx.x];
    int i = blockIdx.x * SCAN_B + t;
    if (i < N_NODES) {
        int r = g_rowptr[i] + offset;
        g_rowptr[i] = r;
        g_cursor[i] = r;
        g_dinv[i] = rsqrtf((float)g_cnt[i] + 1.f);
    }
}

__global__ void fill_kernel(const int* __restrict__ src, const int* __restrict__ dst) {
    int e = blockIdx.x * blockDim.x + threadIdx.x;
    if (e < N_EDGES) {
        int s = src[e];
        int d = dst[e];
        int pos = atomicAdd(&g_cursor[d], 1);
        g_eidx[pos] = s;
    }
}

// ---------------- layer-1 input split (fp32 -> bf16 hi/lo, K pad 75->80) ----
__global__ void prep_kernel(const float* __restrict__ x) {
    int id = blockIdx.x * blockDim.x + threadIdx.x;
    if (id >= N_NODES * 40) return;
    int n = id / 40, p = id - n * 40;
    int k2 = p * 2;
    float v0 = (k2 < 75) ? x[n * 75 + k2] : 0.f;
    float v1 = (k2 + 1 < 75) ? x[n * 75 + k2 + 1] : 0.f;
    uint32_t lo;
    uint32_t hi = split_hi2(v0, v1, lo);
    *(uint32_t*)&g_xhi[n * 80 + k2] = hi;
    *(uint32_t*)&g_xlo[n * 80 + k2] = lo;
}

// ---------------- wmma GEMM: h' = (X' @ W') * dinv ------------------------
// Persistent, cp.async double-buffered X tiles (128 nodes), W' staged once.
// Split-bf16: D = Xhi@Whi + Xhi@Wlo + Xlo@Whi, fp32 accum (tensor pipe).
// BN affine folded into W' + seed t[c]; epilogue (acc + t[c]) * dinv[n].
template <int K, bool FROM_Y>
__global__ __launch_bounds__(256) void gemm_wmma_kernel(const float* __restrict__ W,
                                                        const float* __restrict__ gam,
                                                        const float* __restrict__ bet,
                                                        int rdp, int wrp) {
    constexpr int K_PAD = (K + 15) & ~15;   // 80 or 64
    constexpr int KS    = K_PAD / 16;       // 5 or 4
    constexpr int A_ELE = 128 * K_PAD;      // halves per A tensor
    constexpr int CPR   = K_PAD / 8;        // 16B chunks per row

    extern __shared__ __align__(16) char smem[];
    float* s_t  = (float*)smem;             // 64
    float* s_a  = s_t + 64;
    float* s_dd = s_a + 64;
    __nv_bfloat16* Wh  = (__nv_bfloat16*)(smem + 1024);
    __nv_bfloat16* Wl  = Wh + K_PAD * HID;
    __nv_bfloat16* A0h = Wl + K_PAD * HID;
    __nv_bfloat16* A0l = A0h + A_ELE;
    __nv_bfloat16* A1h = A0l + A_ELE;
    __nv_bfloat16* A1l = A1h + A_ELE;
    float* epi = (float*)(A1l + A_ELE);     // 8 warps * 256 floats

    int tid = threadIdx.x, wid = tid >> 5, lid = tid & 31;

    if (tid < 2 * HID) g_stats[wrp][tid] = 0.f;
    if (FROM_Y && tid < HID) {
        float mean = g_stats[rdp][tid] * (1.f / N_NODES);
        float var  = g_stats[rdp][HID + tid] * (1.f / N_NODES) - mean * mean;
        float a = gam[tid] * rsqrtf(var + BN_EPS);
        s_a[tid]  = a;
        s_dd[tid] = bet[tid] - mean * a;
    }
    __syncthreads();

    // stage W' = a[k]*W (split hi/lo), zero-pad k >= K
    for (int i = tid; i < K_PAD * HID; i += 256) {
        int k = i >> 6;
        float w = 0.f;
        if (k < K) {
            w = W[i];
            if (FROM_Y) w *= s_a[k];
        }
        __nv_bfloat16 wh = __float2bfloat16(w);
        Wh[i] = wh;
        Wl[i] = __float2bfloat16(w - __bfloat162float(wh));
    }
    if (tid < HID) {
        float t = 0.f;
        if (FROM_Y) {
            for (int k = 0; k < K; k++) t += s_dd[k] * W[k * HID + tid];
        }
        s_t[tid] = t;
    }

    const __nv_bfloat16* XH = FROM_Y ? g_yhi : g_xhi;
    const __nv_bfloat16* XL = FROM_Y ? g_ylo : g_xlo;

    auto stage = [&](__nv_bfloat16* Ah, __nv_bfloat16* Al, int t0) {
        int gb = t0 * 128;
        for (int ch = tid; ch < 128 * CPR; ch += 256) {
            int row = ch / CPR;
            int off = (ch - row * CPR) * 8;
            int gr = min(gb + row, N_NODES - 1);
            CP_ASYNC16(smem_u32(Ah + row * K_PAD + off), XH + (size_t)gr * K_PAD + off);
            CP_ASYNC16(smem_u32(Al + row * K_PAD + off), XL + (size_t)gr * K_PAD + off);
        }
        CP_COMMIT();
    };

    __nv_bfloat16* bAh = A0h;
    __nv_bfloat16* bAl = A0l;
    __nv_bfloat16* bBh = A1h;
    __nv_bfloat16* bBl = A1l;
    int tile = blockIdx.x;
    stage(bAh, bAl, tile);                  // GEMM_GRID < GEMM_TILES always

    float* patch = epi + wid * 256;

    for (; tile < GEMM_TILES; tile += GEMM_GRID) {
        int nxt = tile + GEMM_GRID;
        if (nxt < GEMM_TILES) stage(bBh, bBl, nxt);
        else                  CP_COMMIT();
        CP_WAIT1();
        __syncthreads();                    // also orders W'/s_t on first iter

        wmma::fragment<wmma::accumulator, 16, 16, 16, float> acc[4];
#pragma unroll
        for (int nc = 0; nc < 4; nc++) wmma::fill_fragment(acc[nc], 0.f);

        const __nv_bfloat16* Arow_h = bAh + wid * 16 * K_PAD;
        const __nv_bfloat16* Arow_l = bAl + wid * 16 * K_PAD;

#pragma unroll
        for (int ks = 0; ks < KS; ks++) {
            wmma::fragment<wmma::matrix_a, 16, 16, 16, __nv_bfloat16, wmma::row_major> ah, al;
            wmma::load_matrix_sync(ah, Arow_h + ks * 16, K_PAD);
            wmma::load_matrix_sync(al, Arow_l + ks * 16, K_PAD);
#pragma unroll
            for (int nc = 0; nc < 4; nc++) {
                wmma::fragment<wmma::matrix_b, 16, 16, 16, __nv_bfloat16, wmma::row_major> bh, bl;
                wmma::load_matrix_sync(bh, Wh + ks * 16 * HID + nc * 16, HID);
                wmma::load_matrix_sync(bl, Wl + ks * 16 * HID + nc * 16, HID);
                wmma::mma_sync(acc[nc], ah, bh, acc[nc]);
                wmma::mma_sync(acc[nc], ah, bl, acc[nc]);
                wmma::mma_sync(acc[nc], al, bh, acc[nc]);
            }
        }

        // epilogue: per-warp 16x16 patch; out = (acc + t[c]) * dinv[row]
        int base = tile * 128;
#pragma unroll
        for (int nc = 0; nc < 4; nc++) {
            wmma::store_matrix_sync(patch, acc[nc], 16, wmma::mem_row_major);
            __syncwarp();
            int row = lid >> 1;
            int c8  = (lid & 1) * 8;
            int gn = base + wid * 16 + row;
            if (gn < N_NODES) {
                float dv = g_dinv[gn];
                int cc = nc * 16 + c8;
                const float* p = patch + row * 16 + c8;
                float4 o0, o1;
                o0.x = (p[0] + s_t[cc + 0]) * dv;
                o0.y = (p[1] + s_t[cc + 1]) * dv;
                o0.z = (p[2] + s_t[cc + 2]) * dv;
                o0.w = (p[3] + s_t[cc + 3]) * dv;
                o1.x = (p[4] + s_t[cc + 4]) * dv;
                o1.y = (p[5] + s_t[cc + 5]) * dv;
                o1.z = (p[6] + s_t[cc + 6]) * dv;
                o1.w = (p[7] + s_t[cc + 7]) * dv;
                *(float4*)&g_h[(size_t)gn * HID + cc]     = o0;
                *(float4*)&g_h[(size_t)gn * HID + cc + 4] = o1;
            }
            __syncwarp();
        }

        __syncthreads();                    // all reads of bufA done before restage
        __nv_bfloat16* th = bAh; bAh = bBh; bBh = th;
        __nv_bfloat16* tl = bAl; bAl = bBl; bBl = tl;
    }
}

// ---------------- gather aggregation + relu + BN stats ----------------
__global__ __launch_bounds__(256) void gather_kernel(const float* __restrict__ bias,
                                                     int wrp) {
    __shared__ float s_b[HID];
    __shared__ float sm_s[16][HID + 4];
    __shared__ float sm_q[16][HID + 4];

    int tid   = threadIdx.x;
    int grp   = tid >> 4;
    int lane  = tid & 15;
    unsigned hmask = 0xFFFFu << ((tid & 31) & 16);
    int c4    = lane * 4;

    if (tid < HID) s_b[tid] = bias[tid];
    __syncthreads();
    float4 bb = *(const float4*)&s_b[c4];

    float4 s4 = {0.f, 0.f, 0.f, 0.f};
    float4 q4 = {0.f, 0.f, 0.f, 0.f};

    for (int tile = blockIdx.x; tile < N_TILES; tile += GATH_GRID) {
        int n = tile * 16 + grp;
        float dv = g_dinv[n];

        float4 acc = *(const float4*)&g_h[(size_t)n * HID + c4];

        int start = g_rowptr[n];
        int len   = g_cnt[n];

        int pre = (lane < len) ? g_eidx[start + lane] : N_NODES;

        for (int j0 = 0; j0 < len; j0 += 16) {
            int sidx = pre;
            int nj = j0 + 16 + lane;
            pre = (nj < len) ? g_eidx[start + nj] : N_NODES;

#pragma unroll
            for (int j = 0; j < 4; j++) {
                int s = __shfl_sync(hmask, sidx, j, 16);
                float4 hv = *(const float4*)&g_h[(size_t)s * HID + c4];
                acc.x += hv.x; acc.y += hv.y;
                acc.z += hv.z; acc.w += hv.w;
            }
            if (len > j0 + 4) {
#pragma unroll
                for (int j = 4; j < 8; j++) {
                    int s = __shfl_sync(hmask, sidx, j, 16);
                    float4 hv = *(const float4*)&g_h[(size_t)s * HID + c4];
                    acc.x += hv.x; acc.y += hv.y;
                    acc.z += hv.z; acc.w += hv.w;
                }
            }
            if (len > j0 + 8) {
#pragma unroll
                for (int j = 8; j < 12; j++) {
                    int s = __shfl_sync(hmask, sidx, j, 16);
                    float4 hv = *(const float4*)&g_h[(size_t)s * HID + c4];
                    acc.x += hv.x; acc.y += hv.y;
                    acc.z += hv.z; acc.w += hv.w;
                }
            }
            if (len > j0 + 12) {
#pragma unroll
                for (int j = 12; j < 16; j++) {
                    int s = __shfl_sync(hmask, sidx, j, 16);
                    float4 hv = *(const float4*)&g_h[(size_t)s * HID + c4];
                    acc.x += hv.x; acc.y += hv.y;
                    acc.z += hv.z; acc.w += hv.w;
                }
            }
        }

        acc.x = fmaxf(acc.x * dv + bb.x, 0.f);
        acc.y = fmaxf(acc.y * dv + bb.y, 0.f);
        acc.z = fmaxf(acc.z * dv + bb.z, 0.f);
        acc.w = fmaxf(acc.w * dv + bb.w, 0.f);
        *(float4*)&g_y[(size_t)n * HID + c4] = acc;

        // split-bf16 output for the next wmma GEMM
        uint32_t lo0, lo1;
        uint32_t hi0 = split_hi2(acc.x, acc.y, lo0);
        uint32_t hi1 = split_hi2(acc.z, acc.w, lo1);
        *(uint2*)&g_yhi[(size_t)n * HID + c4] = make_uint2(hi0, hi1);
        *(uint2*)&g_ylo[(size_t)n * HID + c4] = make_uint2(lo0, lo1);

        s4.x += acc.x; q4.x += acc.x * acc.x;
        s4.y += acc.y; q4.y += acc.y * acc.y;
        s4.z += acc.z; q4.z += acc.z * acc.z;
        s4.w += acc.w; q4.w += acc.w * acc.w;
    }

    sm_s[grp][c4 + 0] = s4.x; sm_q[grp][c4 + 0] = q4.x;
    sm_s[grp][c4 + 1] = s4.y; sm_q[grp][c4 + 1] = q4.y;
    sm_s[grp][c4 + 2] = s4.z; sm_q[grp][c4 + 2] = q4.z;
    sm_s[grp][c4 + 3] = s4.w; sm_q[grp][c4 + 3] = q4.w;
    __syncthreads();
    if (tid < HID) {
        float s = 0.f, q = 0.f;
#pragma unroll
        for (int r = 0; r < 16; r++) {
            s += sm_s[r][tid];
            q += sm_q[r][tid];
        }
        asm volatile("red.global.add.f32 [%0], %1;" :: "l"(&g_stats[wrp][tid]), "f"(s) : "memory");
        asm volatile("red.global.add.f32 [%0], %1;" :: "l"(&g_stats[wrp][HID + tid]), "f"(q) : "memory");
    }
}

// ---------------- global add pool (applies final BN affine) ----------------
__global__ __launch_bounds__(256) void pool_kernel(const int* __restrict__ batch,
                                                   float* __restrict__ out,
                                                   const float* __restrict__ gam,
                                                   const float* __restrict__ bet) {
    __shared__ float s_a[HID];
    __shared__ float s_d[HID];
    int tid = threadIdx.x;
    if (tid < HID) {
        float mean = g_stats[1][tid] * (1.f / N_NODES);
        float var  = g_stats[1][HID + tid] * (1.f / N_NODES) - mean * mean;
        float a = gam[tid] * rsqrtf(var + BN_EPS);
        s_a[tid] = a;
        s_d[tid] = bet[tid] - mean * a;
    }
    __syncthreads();

    int grp = tid >> 4, lane = tid & 15;
    int c4 = lane * 4;
    float4 a4 = *(const float4*)&s_a[c4];
    float4 d4 = *(const float4*)&s_d[c4];

    int base = blockIdx.x * 256 + grp * 16;
    float4 run = {0.f, 0.f, 0.f, 0.f};
    int cur = -1;
    for (int i = 0; i < 16; i++) {
        int n = base + i;
        if (n >= N_NODES) break;
        int bt = batch[n];
        if (bt != cur) {
            if (cur >= 0) {
                asm volatile("red.global.add.v4.f32 [%0], {%1,%2,%3,%4};"
                             :: "l"(&out[cur * HID + c4]),
                                "f"(run.x), "f"(run.y), "f"(run.z), "f"(run.w) : "memory");
            }
            run.x = run.y = run.z = run.w = 0.f;
            cur = bt;
        }
        float4 v = *(const float4*)&g_y[(size_t)n * HID + c4];
        run.x += v.x * a4.x + d4.x;
        run.y += v.y * a4.y + d4.y;
        run.z += v.z * a4.z + d4.z;
        run.w += v.w * a4.w + d4.w;
    }
    if (cur >= 0) {
        asm volatile("red.global.add.v4.f32 [%0], {%1,%2,%3,%4};"
                     :: "l"(&out[cur * HID + c4]),
                        "f"(run.x), "f"(run.y), "f"(run.z), "f"(run.w) : "memory");
    }
}

// ---------------- launch ----------------
extern "C" void kernel_launch(void* const* d_in, const int* in_sizes, int n_in,
                              void* d_out, int out_size) {
    const float* x     = (const float*)d_in[0];
    const int*   src   = (const int*)d_in[1];
    const int*   dst   = (const int*)d_in[2];
    const int*   batch = (const int*)d_in[3];
    const float* W[4];
    const float* b[4];
    const float* g[4];
    const float* be[4];
    for (int i = 0; i < 4; i++) {
        W[i]  = (const float*)d_in[4 + 4 * i];
        b[i]  = (const float*)d_in[5 + 4 * i];
        g[i]  = (const float*)d_in[6 + 4 * i];
        be[i] = (const float*)d_in[7 + 4 * i];
    }
    float* out = (float*)d_out;

    const int NB_EDGES = (N_EDGES + 255) / 256;   // 6250
    const int NB_NODES = (N_NODES + 255) / 256;   // 391
    const int NB_PREP  = (N_NODES * 40 + 255) / 256;

    // smem: 1024 hdr + W'(hi+lo) + 2 double-buffered A(hi+lo) + 8KB epi
    const int SMEM75 = 1024 + 2 * 80 * HID * 2 + 4 * 128 * 80 * 2 + 8192;  // 111616
    const int SMEM64 = 1024 + 2 * 64 * HID * 2 + 4 * 128 * 64 * 2 + 8192;  // 91136
    cudaFuncSetAttribute(gemm_wmma_kernel<75, false>,
                         cudaFuncAttributeMaxDynamicSharedMemorySize, SMEM75);
    cudaFuncSetAttribute(gemm_wmma_kernel<64, true>,
                         cudaFuncAttributeMaxDynamicSharedMemorySize, SMEM64);

    void* p_cnt = nullptr;
    cudaGetSymbolAddress(&p_cnt, g_cnt);
    cudaMemsetAsync(p_cnt, 0, N_NODES * sizeof(int), 0);

    hist_kernel<<<NB_EDGES, 256>>>(dst);
    scan1_kernel<<<SCAN_NB, SCAN_B>>>();
    scan23_kernel<<<SCAN_NB, SCAN_B>>>();   // produces dinv
    prep_kernel<<<NB_PREP, 256>>>(x);       // split layer-1 input

    gemm_wmma_kernel<75, false><<<GEMM_GRID, 256, SMEM75>>>(W[0], nullptr, nullptr, 0, 0);
    fill_kernel<<<NB_EDGES, 256>>>(src, dst);

    // zero row N_NODES of g_h (target of padded gather lanes)
    void* p_h = nullptr;
    cudaGetSymbolAddress(&p_h, g_h);
    cudaMemsetAsync((char*)p_h + (size_t)N_NODES * HID * sizeof(float), 0,
                    HID * sizeof(float), 0);

    gather_kernel<<<GATH_GRID, 256>>>(b[0], 0);

    for (int l = 1; l < 4; l++) {
        gemm_wmma_kernel<64, true><<<GEMM_GRID, 256, SMEM64>>>(W[l], g[l - 1], be[l - 1],
                                                               (l - 1) & 1, l & 1);
        gather_kernel<<<GATH_GRID, 256>>>(b[l], l & 1);
    }

    cudaMemsetAsync(d_out, 0, (size_t)out_size * sizeof(float), 0);
    pool_kernel<<<NB_NODES, 256>>>(batch, out, g[3], be[3]);
}

// round 16
// speedup vs baseline: 1.0094x; 1.0094x over previous
#include <cuda_runtime.h>
#include <cuda_bf16.h>
#include <mma.h>
#include <cstdint>

using namespace nvcuda;

#define N_NODES 100000
#define N_EDGES 1600000
#define HID 64
#define NGRAPH 4096
#define BN_EPS 1e-5f
#define SCAN_B 1024
#define SCAN_NB ((N_NODES + SCAN_B - 1) / SCAN_B)   // 98
#define N_TILES (N_NODES / 16)                      // 6250 (exact)
#define GATH_GRID 592
#define GEMM_TILES ((N_NODES + 127) / 128)          // 782
#define GEMM_GRID 296

// ---------------- scratch (device globals; no allocations) ----------------
__device__ __align__(16) float g_h[(N_NODES + 1) * HID]; // h' = h*dinv (+zero row)
__device__ __align__(16) float g_y[N_NODES * HID];       // post-relu (pool input)
__device__ __align__(16) __nv_bfloat16 g_xhi[N_NODES * 80];
__device__ __align__(16) __nv_bfloat16 g_xlo[N_NODES * 80];
__device__ __align__(16) __nv_bfloat16 g_yhi[N_NODES * HID];
__device__ __align__(16) __nv_bfloat16 g_ylo[N_NODES * HID];
__device__ int   g_cnt[N_NODES];
__device__ float g_dinv[N_NODES];
__device__ int   g_rowptr[N_NODES];
__device__ int   g_cursor[N_NODES];
__device__ int   g_eidx[N_EDGES];
__device__ int   g_blksum[SCAN_NB];
__device__ float g_stats[2][2 * HID];

// ---------------- helpers ----------------
__device__ __forceinline__ unsigned smem_u32(const void* p) {
    return (unsigned)__cvta_generic_to_shared(p);
}
#define CP_ASYNC16(s, g) asm volatile("cp.async.cg.shared.global [%0], [%1], 16;" :: "r"(s), "l"(g) : "memory")
#define CP_COMMIT()      asm volatile("cp.async.commit_group;" ::: "memory")
#define CP_WAIT1()       asm volatile("cp.async.wait_group 1;" ::: "memory")

__device__ __forceinline__ uint32_t split_hi2(float a, float b, uint32_t& lo_out) {
    __nv_bfloat16 ha = __float2bfloat16(a);
    __nv_bfloat16 hb = __float2bfloat16(b);
    __nv_bfloat16 la = __float2bfloat16(a - __bfloat162float(ha));
    __nv_bfloat16 lb = __float2bfloat16(b - __bfloat162float(hb));
    __nv_bfloat162 h2; h2.x = ha; h2.y = hb;
    __nv_bfloat162 l2; l2.x = la; l2.y = lb;
    lo_out = *(uint32_t*)&l2;
    return *(uint32_t*)&h2;
}

// ---------------- CSR build ----------------
__global__ void hist_kernel(const int* __restrict__ dst) {
    int e = blockIdx.x * blockDim.x + threadIdx.x;
    if (e < N_EDGES) {
        asm volatile("red.global.add.u32 [%0], %1;"
                     :: "l"(&g_cnt[dst[e]]), "r"(1) : "memory");
    }
}

__global__ __launch_bounds__(SCAN_B) void scan1_kernel() {
    __shared__ int sm[SCAN_B];
    int t = threadIdx.x;
    int i = blockIdx.x * SCAN_B + t;
    int v = (i < N_NODES) ? g_cnt[i] : 0;
    sm[t] = v;
    __syncthreads();
    for (int off = 1; off < SCAN_B; off <<= 1) {
        int x = (t >= off) ? sm[t - off] : 0;
        __syncthreads();
        sm[t] += x;
        __syncthreads();
    }
    if (i < N_NODES) g_rowptr[i] = sm[t] - v;
    if (t == SCAN_B - 1) g_blksum[blockIdx.x] = sm[t];
}

__global__ __launch_bounds__(SCAN_B) void scan23_kernel() {
    __shared__ int sb[128];
    __shared__ int sv[128];
    int t = threadIdx.x;
    if (t < 128) {
        int v = (t < SCAN_NB) ? g_blksum[t] : 0;
        sb[t] = v;
        sv[t] = v;
    }
    __syncthreads();
    for (int off = 1; off < 128; off <<= 1) {
        int x = (t >= off && t < 128) ? sb[t - off] : 0;
        __syncthreads();
        if (t < 128) sb[t] += x;
        __syncthreads();
    }
    int offset = sb[blockIdx.x] - sv[blockIdx.x];
    int i = blockIdx.x * SCAN_B + t;
    if (i < N_NODES) {
        int r = g_rowptr[i] + offset;
        g_rowptr[i] = r;
        g_cursor[i] = r;
        g_dinv[i] = rsqrtf((float)g_cnt[i] + 1.f);
    }
}

__global__ void fill_kernel(const int* __restrict__ src, const int* __restrict__ dst) {
    int e = blockIdx.x * blockDim.x + threadIdx.x;
    if (e < N_EDGES) {
        int s = src[e];
        int d = dst[e];
        int pos = atomicAdd(&g_cursor[d], 1);
        g_eidx[pos] = s;
    }
}

// ---------------- layer-1 input split (fp32 -> bf16 hi/lo, K pad 75->80) ----
__global__ void prep_kernel(const float* __restrict__ x) {
    int id = blockIdx.x * blockDim.x + threadIdx.x;
    if (id >= N_NODES * 40) return;
    int n = id / 40, p = id - n * 40;
    int k2 = p * 2;
    float v0 = (k2 < 75) ? x[n * 75 + k2] : 0.f;
    float v1 = (k2 + 1 < 75) ? x[n * 75 + k2 + 1] : 0.f;
    uint32_t lo;
    uint32_t hi = split_hi2(v0, v1, lo);
    *(uint32_t*)&g_xhi[n * 80 + k2] = hi;
    *(uint32_t*)&g_xlo[n * 80 + k2] = lo;
}

// ---------------- wmma GEMM: h' = (X' @ W') * dinv ------------------------
// Persistent, cp.async double-buffered X tiles (128 nodes), W' staged once.
// Split-bf16: D = Xhi@Whi + Xhi@Wlo + Xlo@Whi, fp32 accum (tensor pipe).
// BN affine folded into W' + seed t[c]; epilogue (acc + t[c]) * dinv[n].
template <int K, bool FROM_Y>
__global__ __launch_bounds__(256) void gemm_wmma_kernel(const float* __restrict__ W,
                                                        const float* __restrict__ gam,
                                                        const float* __restrict__ bet,
                                                        int rdp, int wrp) {
    constexpr int K_PAD = (K + 15) & ~15;   // 80 or 64
    constexpr int KS    = K_PAD / 16;       // 5 or 4
    constexpr int A_ELE = 128 * K_PAD;      // halves per A tensor
    constexpr int CPR   = K_PAD / 8;        // 16B chunks per row

    extern __shared__ __align__(16) char smem[];
    float* s_t  = (float*)smem;             // 64
    float* s_a  = s_t + 64;
    float* s_dd = s_a + 64;
    __nv_bfloat16* Wh  = (__nv_bfloat16*)(smem + 1024);
    __nv_bfloat16* Wl  = Wh + K_PAD * HID;
    __nv_bfloat16* A0h = Wl + K_PAD * HID;
    __nv_bfloat16* A0l = A0h + A_ELE;
    __nv_bfloat16* A1h = A0l + A_ELE;
    __nv_bfloat16* A1l = A1h + A_ELE;
    float* epi = (float*)(A1l + A_ELE);     // 8 warps * 256 floats

    int tid = threadIdx.x, wid = tid >> 5, lid = tid & 31;

    if (tid < 2 * HID) g_stats[wrp][tid] = 0.f;
    if (FROM_Y && tid < HID) {
        float mean = g_stats[rdp][tid] * (1.f / N_NODES);
        float var  = g_stats[rdp][HID + tid] * (1.f / N_NODES) - mean * mean;
        float a = gam[tid] * rsqrtf(var + BN_EPS);
        s_a[tid]  = a;
        s_dd[tid] = bet[tid] - mean * a;
    }
    __syncthreads();

    // stage W' = a[k]*W (split hi/lo), zero-pad k >= K
    for (int i = tid; i < K_PAD * HID; i += 256) {
        int k = i >> 6;
        float w = 0.f;
        if (k < K) {
            w = W[i];
            if (FROM_Y) w *= s_a[k];
        }
        __nv_bfloat16 wh = __float2bfloat16(w);
        Wh[i] = wh;
        Wl[i] = __float2bfloat16(w - __bfloat162float(wh));
    }
    if (tid < HID) {
        float t = 0.f;
        if (FROM_Y) {
            for (int k = 0; k < K; k++) t += s_dd[k] * W[k * HID + tid];
        }
        s_t[tid] = t;
    }

    const __nv_bfloat16* XH = FROM_Y ? g_yhi : g_xhi;
    const __nv_bfloat16* XL = FROM_Y ? g_ylo : g_xlo;

    auto stage = [&](__nv_bfloat16* Ah, __nv_bfloat16* Al, int t0) {
        int gb = t0 * 128;
        for (int ch = tid; ch < 128 * CPR; ch += 256) {
            int row = ch / CPR;
            int off = (ch - row * CPR) * 8;
            int gr = min(gb + row, N_NODES - 1);
            CP_ASYNC16(smem_u32(Ah + row * K_PAD + off), XH + (size_t)gr * K_PAD + off);
            CP_ASYNC16(smem_u32(Al + row * K_PAD + off), XL + (size_t)gr * K_PAD + off);
        }
        CP_COMMIT();
    };

    __nv_bfloat16* bAh = A0h;
    __nv_bfloat16* bAl = A0l;
    __nv_bfloat16* bBh = A1h;
    __nv_bfloat16* bBl = A1l;
    int tile = blockIdx.x;
    stage(bAh, bAl, tile);                  // GEMM_GRID < GEMM_TILES always

    float* patch = epi + wid * 256;

    for (; tile < GEMM_TILES; tile += GEMM_GRID) {
        int nxt = tile + GEMM_GRID;
        if (nxt < GEMM_TILES) stage(bBh, bBl, nxt);
        else                  CP_COMMIT();
        CP_WAIT1();
        __syncthreads();                    // also orders W'/s_t on first iter

        wmma::fragment<wmma::accumulator, 16, 16, 16, float> acc[4];
#pragma unroll
        for (int nc = 0; nc < 4; nc++) wmma::fill_fragment(acc[nc], 0.f);

        const __nv_bfloat16* Arow_h = bAh + wid * 16 * K_PAD;
        const __nv_bfloat16* Arow_l = bAl + wid * 16 * K_PAD;

#pragma unroll
        for (int ks = 0; ks < KS; ks++) {
            wmma::fragment<wmma::matrix_a, 16, 16, 16, __nv_bfloat16, wmma::row_major> ah, al;
            wmma::load_matrix_sync(ah, Arow_h + ks * 16, K_PAD);
            wmma::load_matrix_sync(al, Arow_l + ks * 16, K_PAD);
#pragma unroll
            for (int nc = 0; nc < 4; nc++) {
                wmma::fragment<wmma::matrix_b, 16, 16, 16, __nv_bfloat16, wmma::row_major> bh, bl;
                wmma::load_matrix_sync(bh, Wh + ks * 16 * HID + nc * 16, HID);
                wmma::load_matrix_sync(bl, Wl + ks * 16 * HID + nc * 16, HID);
                wmma::mma_sync(acc[nc], ah, bh, acc[nc]);
                wmma::mma_sync(acc[nc], ah, bl, acc[nc]);
                wmma::mma_sync(acc[nc], al, bh, acc[nc]);
            }
        }

        // epilogue: per-warp 16x16 patch; out = (acc + t[c]) * dinv[row]
        int base = tile * 128;
#pragma unroll
        for (int nc = 0; nc < 4; nc++) {
            wmma::store_matrix_sync(patch, acc[nc], 16, wmma::mem_row_major);
            __syncwarp();
            int row = lid >> 1;
            int c8  = (lid & 1) * 8;
            int gn = base + wid * 16 + row;
            if (gn < N_NODES) {
                float dv = g_dinv[gn];
                int cc = nc * 16 + c8;
                const float* p = patch + row * 16 + c8;
                float4 o0, o1;
                o0.x = (p[0] + s_t[cc + 0]) * dv;
                o0.y = (p[1] + s_t[cc + 1]) * dv;
                o0.z = (p[2] + s_t[cc + 2]) * dv;
                o0.w = (p[3] + s_t[cc + 3]) * dv;
                o1.x = (p[4] + s_t[cc + 4]) * dv;
                o1.y = (p[5] + s_t[cc + 5]) * dv;
                o1.z = (p[6] + s_t[cc + 6]) * dv;
                o1.w = (p[7] + s_t[cc + 7]) * dv;
                *(float4*)&g_h[(size_t)gn * HID + cc]     = o0;
                *(float4*)&g_h[(size_t)gn * HID + cc + 4] = o1;
            }
            __syncwarp();
        }

        __syncthreads();                    // all reads of bufA done before restage
        __nv_bfloat16* th = bAh; bAh = bBh; bBh = th;
        __nv_bfloat16* tl = bAl; bAl = bBl; bBl = tl;
    }
}

// ---------------- gather aggregation + relu + BN stats ----------------
__global__ __launch_bounds__(256) void gather_kernel(const float* __restrict__ bias,
                                                     int wrp) {
    __shared__ float s_b[HID];
    __shared__ float sm_s[16][HID + 4];
    __shared__ float sm_q[16][HID + 4];

    int tid   = threadIdx.x;
    int grp   = tid >> 4;
    int lane  = tid & 15;
    unsigned hmask = 0xFFFFu << ((tid & 31) & 16);
    int c4    = lane * 4;

    if (tid < HID) s_b[tid] = bias[tid];
    __syncthreads();
    float4 bb = *(const float4*)&s_b[c4];

    float4 s4 = {0.f, 0.f, 0.f, 0.f};
    float4 q4 = {0.f, 0.f, 0.f, 0.f};

    for (int tile = blockIdx.x; tile < N_TILES; tile += GATH_GRID) {
        int n = tile * 16 + grp;
        float dv = g_dinv[n];

        float4 acc = *(const float4*)&g_h[(size_t)n * HID + c4];

        int start = g_rowptr[n];
        int len   = g_cnt[n];

        int pre = (lane < len) ? g_eidx[start + lane] : N_NODES;

        for (int j0 = 0; j0 < len; j0 += 16) {
            int sidx = pre;
            int nj = j0 + 16 + lane;
            pre = (nj < len) ? g_eidx[start + nj] : N_NODES;

#pragma unroll
            for (int j = 0; j < 4; j++) {
                int s = __shfl_sync(hmask, sidx, j, 16);
                float4 hv = *(const float4*)&g_h[(size_t)s * HID + c4];
                acc.x += hv.x; acc.y += hv.y;
                acc.z += hv.z; acc.w += hv.w;
            }
            if (len > j0 + 4) {
#pragma unroll
                for (int j = 4; j < 8; j++) {
                    int s = __shfl_sync(hmask, sidx, j, 16);
                    float4 hv = *(const float4*)&g_h[(size_t)s * HID + c4];
                    acc.x += hv.x; acc.y += hv.y;
                    acc.z += hv.z; acc.w += hv.w;
                }
            }
            if (len > j0 + 8) {
#pragma unroll
                for (int j = 8; j < 12; j++) {
                    int s = __shfl_sync(hmask, sidx, j, 16);
                    float4 hv = *(const float4*)&g_h[(size_t)s * HID + c4];
                    acc.x += hv.x; acc.y += hv.y;
                    acc.z += hv.z; acc.w += hv.w;
                }
            }
            if (len > j0 + 12) {
#pragma unroll
                for (int j = 12; j < 16; j++) {
                    int s = __shfl_sync(hmask, sidx, j, 16);
                    float4 hv = *(const float4*)&g_h[(size_t)s * HID + c4];
                    acc.x += hv.x; acc.y += hv.y;
                    acc.z += hv.z; acc.w += hv.w;
                }
            }
        }

        acc.x = fmaxf(acc.x * dv + bb.x, 0.f);
        acc.y = fmaxf(acc.y * dv + bb.y, 0.f);
        acc.z = fmaxf(acc.z * dv + bb.z, 0.f);
        acc.w = fmaxf(acc.w * dv + bb.w, 0.f);
        *(float4*)&g_y[(size_t)n * HID + c4] = acc;

        // split-bf16 output for the next wmma GEMM
        uint32_t lo0, lo1;
        uint32_t hi0 = split_hi2(acc.x, acc.y, lo0);
        uint32_t hi1 = split_hi2(acc.z, acc.w, lo1);
        *(uint2*)&g_yhi[(size_t)n * HID + c4] = make_uint2(hi0, hi1);
        *(uint2*)&g_ylo[(size_t)n * HID + c4] = make_uint2(lo0, lo1);

        s4.x += acc.x; q4.x += acc.x * acc.x;
        s4.y += acc.y; q4.y += acc.y * acc.y;
        s4.z += acc.z; q4.z += acc.z * acc.z;
        s4.w += acc.w; q4.w += acc.w * acc.w;
    }

    sm_s[grp][c4 + 0] = s4.x; sm_q[grp][c4 + 0] = q4.x;
    sm_s[grp][c4 + 1] = s4.y; sm_q[grp][c4 + 1] = q4.y;
    sm_s[grp][c4 + 2] = s4.z; sm_q[grp][c4 + 2] = q4.z;
    sm_s[grp][c4 + 3] = s4.w; sm_q[grp][c4 + 3] = q4.w;
    __syncthreads();
    if (tid < HID) {
        float s = 0.f, q = 0.f;
#pragma unroll
        for (int r = 0; r < 16; r++) {
            s += sm_s[r][tid];
            q += sm_q[r][tid];
        }
        asm volatile("red.global.add.f32 [%0], %1;" :: "l"(&g_stats[wrp][tid]), "f"(s) : "memory");
        asm volatile("red.global.add.f32 [%0], %1;" :: "l"(&g_stats[wrp][HID + tid]), "f"(q) : "memory");
    }
}

// ---------------- global add pool (applies final BN affine) ----------------
__global__ __launch_bounds__(256) void pool_kernel(const int* __restrict__ batch,
                                                   float* __restrict__ out,
                                                   const float* __restrict__ gam,
                                                   const float* __restrict__ bet) {
    __shared__ float s_a[HID];
    __shared__ float s_d[HID];
    int tid = threadIdx.x;
    if (tid < HID) {
        float mean = g_stats[1][tid] * (1.f / N_NODES);
        float var  = g_stats[1][HID + tid] * (1.f / N_NODES) - mean * mean;
        float a = gam[tid] * rsqrtf(var + BN_EPS);
        s_a[tid] = a;
        s_d[tid] = bet[tid] - mean * a;
    }
    __syncthreads();

    int grp = tid >> 4, lane = tid & 15;
    int c4 = lane * 4;
    float4 a4 = *(const float4*)&s_a[c4];
    float4 d4 = *(const float4*)&s_d[c4];

    int base = blockIdx.x * 256 + grp * 16;
    float4 run = {0.f, 0.f, 0.f, 0.f};
    int cur = -1;
    for (int i = 0; i < 16; i++) {
        int n = base + i;
        if (n >= N_NODES) break;
        int bt = batch[n];
        if (bt != cur) {
            if (cur >= 0) {
                asm volatile("red.global.add.v4.f32 [%0], {%1,%2,%3,%4};"
                             :: "l"(&out[cur * HID + c4]),
                                "f"(run.x), "f"(run.y), "f"(run.z), "f"(run.w) : "memory");
            }
            run.x = run.y = run.z = run.w = 0.f;
            cur = bt;
        }
        float4 v = *(const float4*)&g_y[(size_t)n * HID + c4];
        run.x += v.x * a4.x + d4.x;
        run.y += v.y * a4.y + d4.y;
        run.z += v.z * a4.z + d4.z;
        run.w += v.w * a4.w + d4.w;
    }
    if (cur >= 0) {
        asm volatile("red.global.add.v4.f32 [%0], {%1,%2,%3,%4};"
                     :: "l"(&out[cur * HID + c4]),
                        "f"(run.x), "f"(run.y), "f"(run.z), "f"(run.w) : "memory");
    }
}

// ---------------- launch ----------------
extern "C" void kernel_launch(void* const* d_in, const int* in_sizes, int n_in,
                              void* d_out, int out_size) {
    const float* x     = (const float*)d_in[0];
    const int*   src   = (const int*)d_in[1];
    const int*   dst   = (const int*)d_in[2];
    const int*   batch = (const int*)d_in[3];
    const float* W[4];
    const float* b[4];
    const float* g[4];
    const float* be[4];
    for (int i = 0; i < 4; i++) {
        W[i]  = (const float*)d_in[4 + 4 * i];
        b[i]  = (const float*)d_in[5 + 4 * i];
        g[i]  = (const float*)d_in[6 + 4 * i];
        be[i] = (const float*)d_in[7 + 4 * i];
    }
    float* out = (float*)d_out;

    const int NB_EDGES = (N_EDGES + 255) / 256;   // 6250
    const int NB_NODES = (N_NODES + 255) / 256;   // 391
    const int NB_PREP  = (N_NODES * 40 + 255) / 256;

    // smem: 1024 hdr + W'(hi+lo) + 2 double-buffered A(hi+lo) + 8KB epi
    const int SMEM75 = 1024 + 2 * 80 * HID * 2 + 4 * 128 * 80 * 2 + 8192;  // 111616
    const int SMEM64 = 1024 + 2 * 64 * HID * 2 + 4 * 128 * 64 * 2 + 8192;  // 91136
    cudaFuncSetAttribute(gemm_wmma_kernel<75, false>,
                         cudaFuncAttributeMaxDynamicSharedMemorySize, SMEM75);
    cudaFuncSetAttribute(gemm_wmma_kernel<64, true>,
                         cudaFuncAttributeMaxDynamicSharedMemorySize, SMEM64);

    void* p_cnt = nullptr;
    cudaGetSymbolAddress(&p_cnt, g_cnt);
    cudaMemsetAsync(p_cnt, 0, N_NODES * sizeof(int), 0);

    hist_kernel<<<NB_EDGES, 256>>>(dst);
    scan1_kernel<<<SCAN_NB, SCAN_B>>>();
    scan23_kernel<<<SCAN_NB, SCAN_B>>>();   // produces dinv
    prep_kernel<<<NB_PREP, 256>>>(x);       // split layer-1 input

    gemm_wmma_kernel<75, false><<<GEMM_GRID, 256, SMEM75>>>(W[0], nullptr, nullptr, 0, 0);
    fill_kernel<<<NB_EDGES, 256>>>(src, dst);

    // zero row N_NODES of g_h (target of padded gather lanes)
    void* p_h = nullptr;
    cudaGetSymbolAddress(&p_h, g_h);
    cudaMemsetAsync((char*)p_h + (size_t)N_NODES * HID * sizeof(float), 0,
                    HID * sizeof(float), 0);

    gather_kernel<<<GATH_GRID, 256>>>(b[0], 0);

    for (int l = 1; l < 4; l++) {
        gemm_wmma_kernel<64, true><<<GEMM_GRID, 256, SMEM64>>>(W[l], g[l - 1], be[l - 1],
                                                               (l - 1) & 1, l & 1);
        gather_kernel<<<GATH_GRID, 256>>>(b[l], l & 1);
    }

    cudaMemsetAsync(d_out, 0, (size_t)out_size * sizeof(float), 0);
    pool_kernel<<<NB_NODES, 256>>>(batch, out, g[3], be[3]);
}